// round 10
// baseline (speedup 1.0000x reference)
#include <cuda_runtime.h>

#define D 32
#define STEPS 5
#define MAXN 50000
#define MAXE 100000
#define ET 8          // edge types
#define EG 8          // edges per warp (edge kernel)
#define NG 4          // nodes per warp (node kernel)

// ----------------------------- device scratch ------------------------------
__device__ float g_prop[MAXN * D];
__device__ float g_in  [MAXN * D];
__device__ float g_out [MAXN * D];

__device__ int   g_cnt[ET];
__device__ int   g_woff[ET];
__device__ int   g_padBase[ET + 1];
__device__ int   g_padTotal;
__device__ int   g_bucket[MAXE + ET * EG];

__device__ float4 g_Wpk[96 * 32];   // (Wr, Wz, Wt, 0) rows 0..95
__device__ float  g_Wt3[32 * 32];   // Wt rows 64..95 (rp segment)

// ---------------------------------------------------------------------------
// init: prop = emb[token]; zero aggregators; zero type counters
// ---------------------------------------------------------------------------
__global__ void ggnn_init(const int* __restrict__ token,
                          const float* __restrict__ emb,
                          int n) {
    int idx = blockIdx.x * blockDim.x + threadIdx.x;
    if (idx < ET) g_cnt[idx] = 0;
    if (idx >= n * D) return;
    int node = idx >> 5;
    int j    = idx & 31;
    g_prop[idx] = __ldg(&emb[token[node] * D + j]);
    g_in[idx]  = 0.f;
    g_out[idx] = 0.f;
}

// prepack weights: Wpk[m][j] = (Wr[m][j], Wz[m][j], Wt[m][j], 0); Wt3 = Wt rows 64..95
__global__ void ggnn_prepack(const float* __restrict__ Wr,
                             const float* __restrict__ Wz,
                             const float* __restrict__ Wt) {
    int idx = blockIdx.x * blockDim.x + threadIdx.x;   // 0..3071
    if (idx >= 96 * 32) return;
    g_Wpk[idx] = make_float4(__ldg(&Wr[idx]), __ldg(&Wz[idx]), __ldg(&Wt[idx]), 0.f);
    if (idx < 32 * 32) g_Wt3[idx] = __ldg(&Wt[64 * 32 + idx]);
}

// ---------------------------------------------------------------------------
// bucket edges by type (static across steps; rebuilt each replay)
// ---------------------------------------------------------------------------
__global__ void ggnn_count(const int* __restrict__ etype, int e_count) {
    __shared__ int scnt[ET];
    int tid = threadIdx.x;
    if (tid < ET) scnt[tid] = 0;
    __syncthreads();
    int e = blockIdx.x * blockDim.x + tid;
    if (e < e_count) atomicAdd(&scnt[__ldg(&etype[e])], 1);
    __syncthreads();
    if (tid < ET && scnt[tid]) atomicAdd(&g_cnt[tid], scnt[tid]);
}

__global__ void ggnn_prefix() {
    if (threadIdx.x != 0 || blockIdx.x != 0) return;
    int acc = 0;
    for (int t = 0; t < ET; t++) {
        g_padBase[t] = acc;
        g_woff[t] = 0;
        int c  = g_cnt[t];
        int pc = (c + EG - 1) / EG * EG;
        for (int k = c; k < pc; k++) g_bucket[acc + k] = -1;  // sentinels
        acc += pc;
    }
    g_padBase[ET] = acc;
    g_padTotal = acc;
}

__global__ void ggnn_scatter(const int* __restrict__ etype, int e_count) {
    __shared__ int scnt[ET], sbase[ET];
    int tid = threadIdx.x;
    if (tid < ET) scnt[tid] = 0;
    __syncthreads();
    int e = blockIdx.x * blockDim.x + tid;
    int t = 0, loc = 0;
    if (e < e_count) {
        t   = __ldg(&etype[e]);
        loc = atomicAdd(&scnt[t], 1);
    }
    __syncthreads();
    if (tid < ET) sbase[tid] = atomicAdd(&g_woff[tid], scnt[tid]);
    __syncthreads();
    if (e < e_count) g_bucket[g_padBase[t] + sbase[t] + loc] = e;
}

// ---------------------------------------------------------------------------
// edge phase: one warp per EG same-type edges. W row loaded once, used 8x.
// ---------------------------------------------------------------------------
__global__ __launch_bounds__(256)
void ggnn_edge(const int* __restrict__ src,
               const int* __restrict__ dst,
               const float* __restrict__ W_edge) {
    int wid  = (blockIdx.x * blockDim.x + threadIdx.x) >> 5;
    int lane = threadIdx.x & 31;
    int start = wid * EG;
    if (start >= g_padTotal) return;

    // locate type for this aligned chunk (buckets padded to EG multiples)
    int t = 0;
#pragma unroll
    for (int k = 1; k < ET; k++)
        if (start >= g_padBase[k]) t = k;

    const float2* __restrict__ W =
        reinterpret_cast<const float2*>(W_edge + (size_t)t * (D * D * 2));

    int   s[EG], d[EG];
    float h[EG];
#pragma unroll
    for (int g = 0; g < EG; g++) {
        int e = g_bucket[start + g];
        if (e >= 0) {
            s[g] = __ldg(&src[e]);
            d[g] = __ldg(&dst[e]);
            h[g] = g_prop[s[g] * D + lane];
        } else {
            s[g] = -1; d[g] = -1; h[g] = 0.f;
        }
    }

    float a0[EG], a1[EG];
#pragma unroll
    for (int g = 0; g < EG; g++) { a0[g] = 0.f; a1[g] = 0.f; }

#pragma unroll
    for (int i = 0; i < D; i++) {
        float2 w = __ldg(&W[i * D + lane]);
#pragma unroll
        for (int g = 0; g < EG; g++) {
            float hv = __shfl_sync(0xffffffffu, h[g], i);
            a0[g] = fmaf(hv, w.x, a0[g]);
            a1[g] = fmaf(hv, w.y, a1[g]);
        }
    }

#pragma unroll
    for (int g = 0; g < EG; g++) {
        if (s[g] >= 0) {
            atomicAdd(&g_in [d[g] * D + lane], a0[g]);
            atomicAdd(&g_out[s[g] * D + lane], a1[g]);
        }
    }
}

// ---------------------------------------------------------------------------
// node phase: one warp per NG nodes; packed float4 weight rows (Wr,Wz,Wt).
// ---------------------------------------------------------------------------
__device__ __forceinline__ float sigmoidf_(float x) {
    return 1.f / (1.f + __expf(-x));
}

__global__ __launch_bounds__(256)
void ggnn_node(const float* __restrict__ br,
               const float* __restrict__ bz,
               const float* __restrict__ bt,
               float* __restrict__ prop_out,
               int n_count) {
    int wid  = (blockIdx.x * blockDim.x + threadIdx.x) >> 5;
    int lane = threadIdx.x & 31;
    int n0 = wid * NG;
    if (n0 >= n_count) return;

    float fin[NG], fout[NG], p[NG];
#pragma unroll
    for (int g = 0; g < NG; g++) {
        int nid = n0 + g;
        if (nid < n_count) {
            int base = nid * D + lane;
            fin[g]  = g_in[base];   g_in[base]  = 0.f;
            fout[g] = g_out[base];  g_out[base] = 0.f;
            p[g]    = g_prop[base];
        } else { fin[g] = 0.f; fout[g] = 0.f; p[g] = 0.f; }
    }

    float ra[NG], za[NG], ta[NG];
    float brv = __ldg(&br[lane]), bzv = __ldg(&bz[lane]), btv = __ldg(&bt[lane]);
#pragma unroll
    for (int g = 0; g < NG; g++) { ra[g] = brv; za[g] = bzv; ta[g] = btv; }

    // segment 0: in_fea (m 0..31) -> r, z, t
#pragma unroll
    for (int m = 0; m < 32; m++) {
        float4 w = g_Wpk[m * 32 + lane];
#pragma unroll
        for (int g = 0; g < NG; g++) {
            float c = __shfl_sync(0xffffffffu, fin[g], m);
            ra[g] = fmaf(c, w.x, ra[g]);
            za[g] = fmaf(c, w.y, za[g]);
            ta[g] = fmaf(c, w.z, ta[g]);
        }
    }
    // segment 1: out_fea (m 32..63) -> r, z, t
#pragma unroll
    for (int m = 0; m < 32; m++) {
        float4 w = g_Wpk[(32 + m) * 32 + lane];
#pragma unroll
        for (int g = 0; g < NG; g++) {
            float c = __shfl_sync(0xffffffffu, fout[g], m);
            ra[g] = fmaf(c, w.x, ra[g]);
            za[g] = fmaf(c, w.y, za[g]);
            ta[g] = fmaf(c, w.z, ta[g]);
        }
    }
    // segment 2: prop (m 64..95) -> r, z only
#pragma unroll
    for (int m = 0; m < 32; m++) {
        float4 w = g_Wpk[(64 + m) * 32 + lane];
#pragma unroll
        for (int g = 0; g < NG; g++) {
            float c = __shfl_sync(0xffffffffu, p[g], m);
            ra[g] = fmaf(c, w.x, ra[g]);
            za[g] = fmaf(c, w.y, za[g]);
        }
    }

    float rp[NG];
#pragma unroll
    for (int g = 0; g < NG; g++) rp[g] = sigmoidf_(ra[g]) * p[g];

    // segment 2 for t: r*prop against Wt rows 64..95
#pragma unroll
    for (int m = 0; m < 32; m++) {
        float w = g_Wt3[m * 32 + lane];
#pragma unroll
        for (int g = 0; g < NG; g++) {
            float c = __shfl_sync(0xffffffffu, rp[g], m);
            ta[g] = fmaf(c, w, ta[g]);
        }
    }

#pragma unroll
    for (int g = 0; g < NG; g++) {
        int nid = n0 + g;
        if (nid < n_count) {
            float z  = sigmoidf_(za[g]);
            float hh = tanhf(ta[g]);
            prop_out[nid * D + lane] = (1.f - z) * p[g] + z * hh;
        }
    }
}

// ---------------------------------------------------------------------------
// launch
// ---------------------------------------------------------------------------
extern "C" void kernel_launch(void* const* d_in, const int* in_sizes, int n_in,
                              void* d_out, int out_size) {
    const int*   token  = (const int*)  d_in[0];
    const int*   etype  = (const int*)  d_in[1];
    const int*   src    = (const int*)  d_in[2];
    const int*   dst    = (const int*)  d_in[3];
    const float* emb    = (const float*)d_in[4];
    const float* W_edge = (const float*)d_in[5];
    const float* W_r    = (const float*)d_in[6];
    const float* b_r    = (const float*)d_in[7];
    const float* W_z    = (const float*)d_in[8];
    const float* b_z    = (const float*)d_in[9];
    const float* W_t    = (const float*)d_in[10];
    const float* b_t    = (const float*)d_in[11];

    int n = in_sizes[0];
    int e = in_sizes[1];
    float* out = (float*)d_out;

    float* prop_sym = nullptr;
    cudaGetSymbolAddress((void**)&prop_sym, g_prop);

    int init_blocks = (n * D + 255) / 256;
    ggnn_init<<<init_blocks, 256>>>(token, emb, n);
    ggnn_prepack<<<12, 256>>>(W_r, W_z, W_t);

    int ecount_blocks = (e + 255) / 256;
    ggnn_count  <<<ecount_blocks, 256>>>(etype, e);
    ggnn_prefix <<<1, 32>>>();
    ggnn_scatter<<<ecount_blocks, 256>>>(etype, e);

    int padMax      = e + ET * (EG - 1);
    int edge_warps  = (padMax + EG - 1) / EG;
    int edge_blocks = (edge_warps * 32 + 255) / 256;

    int node_warps  = (n + NG - 1) / NG;
    int node_blocks = (node_warps * 32 + 255) / 256;

    for (int step = 0; step < STEPS; step++) {
        ggnn_edge<<<edge_blocks, 256>>>(src, dst, W_edge);
        float* po = (step == STEPS - 1) ? out : prop_sym;
        ggnn_node<<<node_blocks, 256>>>(b_r, b_z, b_t, po, n);
    }
}

// round 11
// speedup vs baseline: 1.0121x; 1.0121x over previous
#include <cuda_runtime.h>

#define D 32
#define STEPS 5
#define MAXN 50000
#define MAXE 100000
#define ET 8          // edge types
#define EG 8          // edges per warp (edge kernel)
#define NG 4          // nodes per warp (node kernel)

// ----------------------------- device scratch ------------------------------
__device__ float g_prop[MAXN * D];
__device__ float g_in  [MAXN * D];
__device__ float g_out [MAXN * D];

__device__ int   g_cnt[ET];
__device__ int   g_woff[ET];
__device__ int   g_padBase[ET + 1];
__device__ int   g_padTotal;
__device__ int   g_bucket[MAXE + ET * EG];

__device__ float4 g_Wpk[96 * 32];   // (Wr, Wz, Wt, 0) rows 0..95
__device__ float  g_Wt3[32 * 32];   // Wt rows 64..95 (rp segment)

// ---------------------------------------------------------------------------
// init: prop = emb[token]; zero aggregators; zero type counters
// ---------------------------------------------------------------------------
__global__ void ggnn_init(const int* __restrict__ token,
                          const float* __restrict__ emb,
                          int n) {
    int idx = blockIdx.x * blockDim.x + threadIdx.x;
    if (idx < ET) g_cnt[idx] = 0;
    if (idx >= n * D) return;
    int node = idx >> 5;
    int j    = idx & 31;
    g_prop[idx] = __ldg(&emb[token[node] * D + j]);
    g_in[idx]  = 0.f;
    g_out[idx] = 0.f;
}

// prepack weights: Wpk[m][j] = (Wr[m][j], Wz[m][j], Wt[m][j], 0); Wt3 = Wt rows 64..95
__global__ void ggnn_prepack(const float* __restrict__ Wr,
                             const float* __restrict__ Wz,
                             const float* __restrict__ Wt) {
    int idx = blockIdx.x * blockDim.x + threadIdx.x;   // 0..3071
    if (idx >= 96 * 32) return;
    g_Wpk[idx] = make_float4(__ldg(&Wr[idx]), __ldg(&Wz[idx]), __ldg(&Wt[idx]), 0.f);
    if (idx < 32 * 32) g_Wt3[idx] = __ldg(&Wt[64 * 32 + idx]);
}

// ---------------------------------------------------------------------------
// bucket edges by type (static across steps; rebuilt each replay)
// ---------------------------------------------------------------------------
__global__ void ggnn_count(const int* __restrict__ etype, int e_count) {
    __shared__ int scnt[ET];
    int tid = threadIdx.x;
    if (tid < ET) scnt[tid] = 0;
    __syncthreads();
    int e = blockIdx.x * blockDim.x + tid;
    if (e < e_count) atomicAdd(&scnt[__ldg(&etype[e])], 1);
    __syncthreads();
    if (tid < ET && scnt[tid]) atomicAdd(&g_cnt[tid], scnt[tid]);
}

__global__ void ggnn_prefix() {
    if (threadIdx.x != 0 || blockIdx.x != 0) return;
    int acc = 0;
    for (int t = 0; t < ET; t++) {
        g_padBase[t] = acc;
        g_woff[t] = 0;
        int c  = g_cnt[t];
        int pc = (c + EG - 1) / EG * EG;
        for (int k = c; k < pc; k++) g_bucket[acc + k] = -1;  // sentinels
        acc += pc;
    }
    g_padBase[ET] = acc;
    g_padTotal = acc;
}

__global__ void ggnn_scatter(const int* __restrict__ etype, int e_count) {
    __shared__ int scnt[ET], sbase[ET];
    int tid = threadIdx.x;
    if (tid < ET) scnt[tid] = 0;
    __syncthreads();
    int e = blockIdx.x * blockDim.x + tid;
    int t = 0, loc = 0;
    if (e < e_count) {
        t   = __ldg(&etype[e]);
        loc = atomicAdd(&scnt[t], 1);
    }
    __syncthreads();
    if (tid < ET) sbase[tid] = atomicAdd(&g_woff[tid], scnt[tid]);
    __syncthreads();
    if (e < e_count) g_bucket[g_padBase[t] + sbase[t] + loc] = e;
}

// ---------------------------------------------------------------------------
// edge phase: one warp per EG same-type edges. W row loaded once, used 8x.
// ---------------------------------------------------------------------------
__global__ __launch_bounds__(256)
void ggnn_edge(const int* __restrict__ src,
               const int* __restrict__ dst,
               const float* __restrict__ W_edge) {
    int wid  = (blockIdx.x * blockDim.x + threadIdx.x) >> 5;
    int lane = threadIdx.x & 31;
    int start = wid * EG;
    if (start >= g_padTotal) return;

    // locate type for this aligned chunk (buckets padded to EG multiples)
    int t = 0;
#pragma unroll
    for (int k = 1; k < ET; k++)
        if (start >= g_padBase[k]) t = k;

    const float2* __restrict__ W =
        reinterpret_cast<const float2*>(W_edge + (size_t)t * (D * D * 2));

    int   s[EG], d[EG];
    float h[EG];
#pragma unroll
    for (int g = 0; g < EG; g++) {
        int e = g_bucket[start + g];
        if (e >= 0) {
            s[g] = __ldg(&src[e]);
            d[g] = __ldg(&dst[e]);
            h[g] = g_prop[s[g] * D + lane];
        } else {
            s[g] = -1; d[g] = -1; h[g] = 0.f;
        }
    }

    float a0[EG], a1[EG];
#pragma unroll
    for (int g = 0; g < EG; g++) { a0[g] = 0.f; a1[g] = 0.f; }

#pragma unroll
    for (int i = 0; i < D; i++) {
        float2 w = __ldg(&W[i * D + lane]);
#pragma unroll
        for (int g = 0; g < EG; g++) {
            float hv = __shfl_sync(0xffffffffu, h[g], i);
            a0[g] = fmaf(hv, w.x, a0[g]);
            a1[g] = fmaf(hv, w.y, a1[g]);
        }
    }

#pragma unroll
    for (int g = 0; g < EG; g++) {
        if (s[g] >= 0) {
            atomicAdd(&g_in [d[g] * D + lane], a0[g]);
            atomicAdd(&g_out[s[g] * D + lane], a1[g]);
        }
    }
}

// ---------------------------------------------------------------------------
// node phase: one warp per NG nodes; packed float4 weight rows (Wr,Wz,Wt).
// ---------------------------------------------------------------------------
__device__ __forceinline__ float sigmoidf_(float x) {
    return 1.f / (1.f + __expf(-x));
}

__global__ __launch_bounds__(256)
void ggnn_node(const float* __restrict__ br,
               const float* __restrict__ bz,
               const float* __restrict__ bt,
               float* __restrict__ prop_out,
               int n_count) {
    int wid  = (blockIdx.x * blockDim.x + threadIdx.x) >> 5;
    int lane = threadIdx.x & 31;
    int n0 = wid * NG;
    if (n0 >= n_count) return;

    float fin[NG], fout[NG], p[NG];
#pragma unroll
    for (int g = 0; g < NG; g++) {
        int nid = n0 + g;
        if (nid < n_count) {
            int base = nid * D + lane;
            fin[g]  = g_in[base];   g_in[base]  = 0.f;
            fout[g] = g_out[base];  g_out[base] = 0.f;
            p[g]    = g_prop[base];
        } else { fin[g] = 0.f; fout[g] = 0.f; p[g] = 0.f; }
    }

    float ra[NG], za[NG], ta[NG];
    float brv = __ldg(&br[lane]), bzv = __ldg(&bz[lane]), btv = __ldg(&bt[lane]);
#pragma unroll
    for (int g = 0; g < NG; g++) { ra[g] = brv; za[g] = bzv; ta[g] = btv; }

    // segment 0: in_fea (m 0..31) -> r, z, t
#pragma unroll
    for (int m = 0; m < 32; m++) {
        float4 w = g_Wpk[m * 32 + lane];
#pragma unroll
        for (int g = 0; g < NG; g++) {
            float c = __shfl_sync(0xffffffffu, fin[g], m);
            ra[g] = fmaf(c, w.x, ra[g]);
            za[g] = fmaf(c, w.y, za[g]);
            ta[g] = fmaf(c, w.z, ta[g]);
        }
    }
    // segment 1: out_fea (m 32..63) -> r, z, t
#pragma unroll
    for (int m = 0; m < 32; m++) {
        float4 w = g_Wpk[(32 + m) * 32 + lane];
#pragma unroll
        for (int g = 0; g < NG; g++) {
            float c = __shfl_sync(0xffffffffu, fout[g], m);
            ra[g] = fmaf(c, w.x, ra[g]);
            za[g] = fmaf(c, w.y, za[g]);
            ta[g] = fmaf(c, w.z, ta[g]);
        }
    }
    // segment 2: prop (m 64..95) -> r, z only
#pragma unroll
    for (int m = 0; m < 32; m++) {
        float4 w = g_Wpk[(64 + m) * 32 + lane];
#pragma unroll
        for (int g = 0; g < NG; g++) {
            float c = __shfl_sync(0xffffffffu, p[g], m);
            ra[g] = fmaf(c, w.x, ra[g]);
            za[g] = fmaf(c, w.y, za[g]);
        }
    }

    float rp[NG];
#pragma unroll
    for (int g = 0; g < NG; g++) rp[g] = sigmoidf_(ra[g]) * p[g];

    // segment 2 for t: r*prop against Wt rows 64..95
#pragma unroll
    for (int m = 0; m < 32; m++) {
        float w = g_Wt3[m * 32 + lane];
#pragma unroll
        for (int g = 0; g < NG; g++) {
            float c = __shfl_sync(0xffffffffu, rp[g], m);
            ta[g] = fmaf(c, w, ta[g]);
        }
    }

#pragma unroll
    for (int g = 0; g < NG; g++) {
        int nid = n0 + g;
        if (nid < n_count) {
            float z  = sigmoidf_(za[g]);
            float hh = tanhf(ta[g]);
            prop_out[nid * D + lane] = (1.f - z) * p[g] + z * hh;
        }
    }
}

// ---------------------------------------------------------------------------
// launch
// ---------------------------------------------------------------------------
extern "C" void kernel_launch(void* const* d_in, const int* in_sizes, int n_in,
                              void* d_out, int out_size) {
    const int*   token  = (const int*)  d_in[0];
    const int*   etype  = (const int*)  d_in[1];
    const int*   src    = (const int*)  d_in[2];
    const int*   dst    = (const int*)  d_in[3];
    const float* emb    = (const float*)d_in[4];
    const float* W_edge = (const float*)d_in[5];
    const float* W_r    = (const float*)d_in[6];
    const float* b_r    = (const float*)d_in[7];
    const float* W_z    = (const float*)d_in[8];
    const float* b_z    = (const float*)d_in[9];
    const float* W_t    = (const float*)d_in[10];
    const float* b_t    = (const float*)d_in[11];

    int n = in_sizes[0];
    int e = in_sizes[1];
    float* out = (float*)d_out;

    float* prop_sym = nullptr;
    cudaGetSymbolAddress((void**)&prop_sym, g_prop);

    int init_blocks = (n * D + 255) / 256;
    ggnn_init<<<init_blocks, 256>>>(token, emb, n);
    ggnn_prepack<<<12, 256>>>(W_r, W_z, W_t);

    int ecount_blocks = (e + 255) / 256;
    ggnn_count  <<<ecount_blocks, 256>>>(etype, e);
    ggnn_prefix <<<1, 32>>>();
    ggnn_scatter<<<ecount_blocks, 256>>>(etype, e);

    int padMax      = e + ET * (EG - 1);
    int edge_warps  = (padMax + EG - 1) / EG;
    int edge_blocks = (edge_warps * 32 + 255) / 256;

    int node_warps  = (n + NG - 1) / NG;
    int node_blocks = (node_warps * 32 + 255) / 256;

    for (int step = 0; step < STEPS; step++) {
        ggnn_edge<<<edge_blocks, 256>>>(src, dst, W_edge);
        float* po = (step == STEPS - 1) ? out : prop_sym;
        ggnn_node<<<node_blocks, 256>>>(b_r, b_z, b_t, po, n);
    }
}